// round 8
// baseline (speedup 1.0000x reference)
#include <cuda_runtime.h>
#include <cstdint>

// ============================================================================
// relu(x @ W^T + b): M=131072, N=256, K=256, fp32.  Base sm_103 target.
// mma.sync.m16n8k8.tf32. CTA 64x256 (full N -> x read ONCE from DRAM),
// KC=32, 2-stage cp.async, 2 CTAs/SM. W pre-converted to tf32(RNA) once.
// R8: software-pipelined fragments (double-buffered LDSM, prefetch kk+1
// during MMAs of kk); fragment loads issued before cp.async prefetch.
// ============================================================================

static constexpr int DK = 256;
static constexpr int DN = 256;
static constexpr int BM = 64;
static constexpr int KC = 32;                 // 32 fp32 = 128B row
static constexpr int THREADS = 256;

static constexpr int A_BYTES = BM * KC * 4;   // 8192
static constexpr int B_BYTES = DN * KC * 4;   // 32768
static constexpr int STAGE_BYTES = A_BYTES + B_BYTES;  // 40960
static constexpr int SMEM_DYN = 2 * STAGE_BYTES;       // 81920

__device__ float W_cvt[DN * DK];              // 256KB static scratch (tf32 bits)

// ---------------------------------------------------------------------------
__device__ __forceinline__ uint32_t smem_u32(const void* p) {
    uint32_t a;
    asm("{ .reg .u64 t; cvta.to.shared.u64 t, %1; cvt.u32.u64 %0, t; }" : "=r"(a) : "l"(p));
    return a;
}
__device__ __forceinline__ void cp_async16(uint32_t dst, const void* src) {
    asm volatile("cp.async.cg.shared.global [%0], [%1], 16;" :: "r"(dst), "l"(src));
}
__device__ __forceinline__ void ldsm_x4(uint32_t* d, uint32_t addr) {
    asm volatile("ldmatrix.sync.aligned.m8n8.x4.shared.b16 {%0,%1,%2,%3}, [%4];"
                 : "=r"(d[0]), "=r"(d[1]), "=r"(d[2]), "=r"(d[3]) : "r"(addr));
}
__device__ __forceinline__ uint32_t tf32r(float v) {
    uint32_t r;
    asm("cvt.rna.tf32.f32 %0, %1;" : "=r"(r) : "f"(v));
    return r;
}
__device__ __forceinline__ uint32_t tf32u(uint32_t v) {
    uint32_t r;
    asm("cvt.rna.tf32.f32 %0, %1;" : "=r"(r) : "f"(__uint_as_float(v)));
    return r;
}
__device__ __forceinline__ void mma_tf32(float* d, const uint32_t* a,
                                         uint32_t b0, uint32_t b1) {
    asm volatile(
        "mma.sync.aligned.m16n8k8.row.col.f32.tf32.tf32.f32 "
        "{%0,%1,%2,%3}, {%4,%5,%6,%7}, {%8,%9}, {%0,%1,%2,%3};"
        : "+f"(d[0]), "+f"(d[1]), "+f"(d[2]), "+f"(d[3])
        : "r"(a[0]), "r"(a[1]), "r"(a[2]), "r"(a[3]), "r"(b0), "r"(b1));
}
__device__ __forceinline__ uint32_t swz(int row, int seg) {
    return (uint32_t)row * 128u + (uint32_t)((seg * 16) ^ ((row & 7) * 16));
}

// ---------------------------------------------------------------------------
__global__ void convert_W_kernel(const float* __restrict__ W) {
    int i = blockIdx.x * 256 + threadIdx.x;
    float4 v = reinterpret_cast<const float4*>(W)[i];
    float4 o;
    o.x = __uint_as_float(tf32r(v.x));
    o.y = __uint_as_float(tf32r(v.y));
    o.z = __uint_as_float(tf32r(v.z));
    o.w = __uint_as_float(tf32r(v.w));
    reinterpret_cast<float4*>(W_cvt)[i] = o;
}

// ---------------------------------------------------------------------------
__global__ __launch_bounds__(THREADS, 2)
void gemm_relu_tf32_kernel(const float* __restrict__ x,
                           const float* __restrict__ bias, float* __restrict__ out) {
    extern __shared__ __align__(1024) char smem_raw[];
    const uint32_t base = smem_u32(smem_raw);

    const int tid = threadIdx.x;
    const int wid = tid >> 5;
    const int lid = tid & 31;
    const int g   = lid >> 2;
    const int t   = lid & 3;
    const int wm  = wid & 1;       // warp m-tile (2 x 32 rows)
    const int wn  = wid >> 1;      // warp n-tile (4 x 64 cols)
    const int m0  = blockIdx.x * BM;

    // ldmatrix lane role
    const int mx = lid >> 3;
    const int r  = lid & 7;
    const uint32_t xr = (uint32_t)(r * 16);

    uint32_t a_row[2], b_row[4];
    #pragma unroll
    for (int mt = 0; mt < 2; mt++)
        a_row[mt] = (uint32_t)(wm * 32 + mt * 16 + (mx & 1) * 8 + r) * 128u;
    #pragma unroll
    for (int ntp = 0; ntp < 4; ntp++)
        b_row[ntp] = (uint32_t)(wn * 64 + ntp * 16 + (mx >> 1) * 8 + r) * 128u;
    const uint32_t a_sel = (uint32_t)((mx >> 1) * 16);
    const uint32_t b_sel = (uint32_t)((mx & 1) * 16);

    // load roles: A 2 float4/thread, B 8 float4/thread
    const int lrow = tid >> 3;       // 0..31
    const int lseg = tid & 7;        // 0..7

    // ---- prologue: stage chunk 0 into stage 0
    #pragma unroll
    for (int i = 0; i < 2; i++) {
        int row = i * 32 + lrow;
        cp_async16(base + swz(row, lseg), x + (size_t)(m0 + row) * DK + lseg * 4);
    }
    #pragma unroll
    for (int i = 0; i < 8; i++) {
        int row = i * 32 + lrow;
        cp_async16(base + A_BYTES + swz(row, lseg), W_cvt + (size_t)row * DK + lseg * 4);
    }
    asm volatile("cp.async.commit_group;" ::: "memory");

    float acc[2][8][4];
    #pragma unroll
    for (int mt = 0; mt < 2; mt++)
        #pragma unroll
        for (int nt = 0; nt < 8; nt++)
            #pragma unroll
            for (int j = 0; j < 4; j++) acc[mt][nt][j] = 0.0f;

    // fragment double buffers
    uint32_t aF[2][2][4];     // [buf][mt][4]
    uint32_t bF[2][4][4];     // [buf][ntp][4]

    #pragma unroll
    for (int kc = 0; kc < 8; kc++) {
        asm volatile("cp.async.wait_group 0;" ::: "memory");
        __syncthreads();

        const uint32_t As = base + (uint32_t)(kc & 1) * STAGE_BYTES;
        const uint32_t Bs = As + A_BYTES;

        // fragments for kk=0 FIRST (latency-critical), buffer 0
        {
            const uint32_t acol = (a_sel) ^ xr;
            const uint32_t bcol = (b_sel) ^ xr;
            #pragma unroll
            for (int mt = 0; mt < 2; mt++)
                ldsm_x4(aF[0][mt], As + a_row[mt] + acol);
            #pragma unroll
            for (int ntp = 0; ntp < 4; ntp++)
                ldsm_x4(bF[0][ntp], Bs + b_row[ntp] + bcol);
            #pragma unroll
            for (int mt = 0; mt < 2; mt++)
                #pragma unroll
                for (int j = 0; j < 4; j++) aF[0][mt][j] = tf32u(aF[0][mt][j]);
        }

        // then issue next-chunk prefetch (full chunk of slack remains)
        if (kc < 7) {
            const uint32_t Ad = base + (uint32_t)((kc + 1) & 1) * STAGE_BYTES;
            const uint32_t Bd = Ad + A_BYTES;
            const int k1 = (kc + 1) * KC;
            #pragma unroll
            for (int i = 0; i < 2; i++) {
                int row = i * 32 + lrow;
                cp_async16(Ad + swz(row, lseg),
                           x + (size_t)(m0 + row) * DK + k1 + lseg * 4);
            }
            #pragma unroll
            for (int i = 0; i < 8; i++) {
                int row = i * 32 + lrow;
                cp_async16(Bd + swz(row, lseg), W_cvt + (size_t)row * DK + k1 + lseg * 4);
            }
            asm volatile("cp.async.commit_group;" ::: "memory");
        }

        #pragma unroll
        for (int kk = 0; kk < 4; kk++) {
            const int cur = kk & 1, nxt = cur ^ 1;

            // prefetch fragments for kk+1 while MMAs of kk execute
            if (kk < 3) {
                const uint32_t acol = ((uint32_t)((kk + 1) * 32) + a_sel) ^ xr;
                const uint32_t bcol = ((uint32_t)((kk + 1) * 32) + b_sel) ^ xr;
                #pragma unroll
                for (int mt = 0; mt < 2; mt++)
                    ldsm_x4(aF[nxt][mt], As + a_row[mt] + acol);
                #pragma unroll
                for (int ntp = 0; ntp < 4; ntp++)
                    ldsm_x4(bF[nxt][ntp], Bs + b_row[ntp] + bcol);
            }

            #pragma unroll
            for (int ntp = 0; ntp < 4; ntp++) {
                mma_tf32(acc[0][2 * ntp],     aF[cur][0], bF[cur][ntp][0], bF[cur][ntp][1]);
                mma_tf32(acc[1][2 * ntp],     aF[cur][1], bF[cur][ntp][0], bF[cur][ntp][1]);
                mma_tf32(acc[0][2 * ntp + 1], aF[cur][0], bF[cur][ntp][2], bF[cur][ntp][3]);
                mma_tf32(acc[1][2 * ntp + 1], aF[cur][1], bF[cur][ntp][2], bF[cur][ntp][3]);
            }

            // convert next A fragments after current MMAs are queued
            if (kk < 3) {
                #pragma unroll
                for (int mt = 0; mt < 2; mt++)
                    #pragma unroll
                    for (int j = 0; j < 4; j++) aF[nxt][mt][j] = tf32u(aF[nxt][mt][j]);
            }
        }
    }

    // ---- epilogue: bias + relu, float2 stores
    const int m_base = m0 + wm * 32;
    const int n_base = wn * 64;
    #pragma unroll
    for (int nt = 0; nt < 8; nt++) {
        const int col = n_base + nt * 8 + 2 * t;
        const float2 bv = *reinterpret_cast<const float2*>(bias + col);
        #pragma unroll
        for (int mt = 0; mt < 2; mt++) {
            const int row0 = m_base + mt * 16 + g;
            float2 v0;
            v0.x = fmaxf(acc[mt][nt][0] + bv.x, 0.0f);
            v0.y = fmaxf(acc[mt][nt][1] + bv.y, 0.0f);
            *reinterpret_cast<float2*>(out + (size_t)row0 * DN + col) = v0;
            float2 v1;
            v1.x = fmaxf(acc[mt][nt][2] + bv.x, 0.0f);
            v1.y = fmaxf(acc[mt][nt][3] + bv.y, 0.0f);
            *reinterpret_cast<float2*>(out + (size_t)(row0 + 8) * DN + col) = v1;
        }
    }
}

// ---------------------------------------------------------------------------
extern "C" void kernel_launch(void* const* d_in, const int* in_sizes, int n_in,
                              void* d_out, int out_size) {
    const float* x = (const float*)d_in[0];
    const float* W = (const float*)d_in[1];
    const float* b = (const float*)d_in[2];
    float* out = (float*)d_out;

    int Brows = in_sizes[0] / DK;     // 131072
    int grid  = Brows / BM;           // 2048

    convert_W_kernel<<<DN * DK / 4 / 256, 256>>>(W);   // 64 blocks

    cudaFuncSetAttribute(gemm_relu_tf32_kernel,
                         cudaFuncAttributeMaxDynamicSharedMemorySize, SMEM_DYN);
    gemm_relu_tf32_kernel<<<grid, THREADS, SMEM_DYN>>>(x, b, out);
}

// round 9
// speedup vs baseline: 1.3984x; 1.3984x over previous
#include <cuda_runtime.h>
#include <cstdint>

// ============================================================================
// relu(x @ W^T + b): M=131072, N=256, K=256, fp32.  Base sm_103 target.
// mma.sync.m16n8k8.tf32. CTA 64x128, KC=32, 3-stage cp.async (prefetch 2),
// 3 CTAs/SM (occ 35%). W pre-converted to tf32(RNA) once -> zero B cvt.
// R9: grid(2, 2048) -- consecutive bids = the two N-halves of one m-tile,
// co-resident in a wave => x fetched from DRAM ~once, re-read served by L2.
// (R7 had grid(2048,2): halves temporally separated => x DRAM-read twice.)
// ============================================================================

static constexpr int DK = 256;
static constexpr int DN = 256;
static constexpr int BM = 64;
static constexpr int BN = 128;
static constexpr int KC = 32;                 // 32 fp32 = 128B row
static constexpr int THREADS = 256;
static constexpr int NSTAGE = 3;

static constexpr int A_BYTES = BM * KC * 4;   // 8192
static constexpr int B_BYTES = BN * KC * 4;   // 16384
static constexpr int STAGE_BYTES = A_BYTES + B_BYTES;   // 24576
static constexpr int SMEM_DYN = NSTAGE * STAGE_BYTES;   // 73728

__device__ float W_cvt[DN * DK];              // 256KB static scratch (tf32 bits)

// ---------------------------------------------------------------------------
__device__ __forceinline__ uint32_t smem_u32(const void* p) {
    uint32_t a;
    asm("{ .reg .u64 t; cvta.to.shared.u64 t, %1; cvt.u32.u64 %0, t; }" : "=r"(a) : "l"(p));
    return a;
}
__device__ __forceinline__ void cp_async16(uint32_t dst, const void* src) {
    asm volatile("cp.async.cg.shared.global [%0], [%1], 16;" :: "r"(dst), "l"(src));
}
__device__ __forceinline__ void ldsm_x4(uint32_t* d, uint32_t addr) {
    asm volatile("ldmatrix.sync.aligned.m8n8.x4.shared.b16 {%0,%1,%2,%3}, [%4];"
                 : "=r"(d[0]), "=r"(d[1]), "=r"(d[2]), "=r"(d[3]) : "r"(addr));
}
__device__ __forceinline__ uint32_t tf32r(float v) {
    uint32_t r;
    asm("cvt.rna.tf32.f32 %0, %1;" : "=r"(r) : "f"(v));
    return r;
}
__device__ __forceinline__ uint32_t tf32u(uint32_t v) {
    uint32_t r;
    asm("cvt.rna.tf32.f32 %0, %1;" : "=r"(r) : "f"(__uint_as_float(v)));
    return r;
}
__device__ __forceinline__ void mma_tf32(float* d, const uint32_t* a,
                                         uint32_t b0, uint32_t b1) {
    asm volatile(
        "mma.sync.aligned.m16n8k8.row.col.f32.tf32.tf32.f32 "
        "{%0,%1,%2,%3}, {%4,%5,%6,%7}, {%8,%9}, {%0,%1,%2,%3};"
        : "+f"(d[0]), "+f"(d[1]), "+f"(d[2]), "+f"(d[3])
        : "r"(a[0]), "r"(a[1]), "r"(a[2]), "r"(a[3]), "r"(b0), "r"(b1));
}
__device__ __forceinline__ uint32_t swz(int row, int seg) {
    return (uint32_t)row * 128u + (uint32_t)((seg * 16) ^ ((row & 7) * 16));
}

// ---------------------------------------------------------------------------
__global__ void convert_W_kernel(const float* __restrict__ W) {
    int i = blockIdx.x * 256 + threadIdx.x;
    float4 v = reinterpret_cast<const float4*>(W)[i];
    float4 o;
    o.x = __uint_as_float(tf32r(v.x));
    o.y = __uint_as_float(tf32r(v.y));
    o.z = __uint_as_float(tf32r(v.z));
    o.w = __uint_as_float(tf32r(v.w));
    reinterpret_cast<float4*>(W_cvt)[i] = o;
}

// ---------------------------------------------------------------------------
__global__ __launch_bounds__(THREADS, 3)
void gemm_relu_tf32_kernel(const float* __restrict__ x,
                           const float* __restrict__ bias, float* __restrict__ out) {
    extern __shared__ __align__(1024) char smem_raw[];
    const uint32_t base = smem_u32(smem_raw);

    const int tid = threadIdx.x;
    const int wid = tid >> 5;
    const int lid = tid & 31;
    const int g   = lid >> 2;
    const int t   = lid & 3;
    const int wm  = wid & 1;       // warp m-tile (2 x 32 rows)
    const int wn  = wid >> 1;      // warp n-tile (4 x 32 cols)
    const int n0  = blockIdx.x * BN;      // N-split is the FAST grid dim
    const int m0  = blockIdx.y * BM;
    const float* Wp = W_cvt + (size_t)n0 * DK;

    // ldmatrix lane role
    const int mx = lid >> 3;
    const int r  = lid & 7;
    const uint32_t xr = (uint32_t)(r * 16);

    uint32_t a_row[2], b_row[2];
    #pragma unroll
    for (int mt = 0; mt < 2; mt++)
        a_row[mt] = (uint32_t)(wm * 32 + mt * 16 + (mx & 1) * 8 + r) * 128u;
    #pragma unroll
    for (int ntp = 0; ntp < 2; ntp++)
        b_row[ntp] = (uint32_t)(wn * 32 + ntp * 16 + (mx >> 1) * 8 + r) * 128u;
    const uint32_t a_sel = (uint32_t)((mx >> 1) * 16);
    const uint32_t b_sel = (uint32_t)((mx & 1) * 16);

    // load roles: A 2 float4/thread, B 4 float4/thread
    const int lrow = tid >> 3;       // 0..31
    const int lseg = tid & 7;        // 0..7

    // ---- prologue: stage chunks 0,1 into stages 0,1
    #pragma unroll
    for (int pc = 0; pc < 2; pc++) {
        const uint32_t S = base + (uint32_t)pc * STAGE_BYTES;
        const int k0 = pc * KC;
        #pragma unroll
        for (int i = 0; i < 2; i++) {
            int row = i * 32 + lrow;
            cp_async16(S + swz(row, lseg), x + (size_t)(m0 + row) * DK + k0 + lseg * 4);
        }
        #pragma unroll
        for (int i = 0; i < 4; i++) {
            int row = i * 32 + lrow;
            cp_async16(S + A_BYTES + swz(row, lseg), Wp + (size_t)row * DK + k0 + lseg * 4);
        }
        asm volatile("cp.async.commit_group;" ::: "memory");
    }

    float acc[2][4][4];
    #pragma unroll
    for (int mt = 0; mt < 2; mt++)
        #pragma unroll
        for (int nt = 0; nt < 4; nt++)
            #pragma unroll
            for (int j = 0; j < 4; j++) acc[mt][nt][j] = 0.0f;

    int stage = 0, dst = 2;
    #pragma unroll
    for (int kc = 0; kc < 8; kc++) {
        if (kc < 7)
            asm volatile("cp.async.wait_group 1;" ::: "memory");
        else
            asm volatile("cp.async.wait_group 0;" ::: "memory");  // drain last chunk
        __syncthreads();

        const uint32_t As = base + (uint32_t)stage * STAGE_BYTES;
        const uint32_t Bs = As + A_BYTES;

        if (kc < 6) {
            const uint32_t Ad = base + (uint32_t)dst * STAGE_BYTES;
            const int k2 = (kc + 2) * KC;
            #pragma unroll
            for (int i = 0; i < 2; i++) {
                int row = i * 32 + lrow;
                cp_async16(Ad + swz(row, lseg),
                           x + (size_t)(m0 + row) * DK + k2 + lseg * 4);
            }
            #pragma unroll
            for (int i = 0; i < 4; i++) {
                int row = i * 32 + lrow;
                cp_async16(Ad + A_BYTES + swz(row, lseg),
                           Wp + (size_t)row * DK + k2 + lseg * 4);
            }
            asm volatile("cp.async.commit_group;" ::: "memory");
        }

        #pragma unroll
        for (int kk = 0; kk < 4; kk++) {
            const uint32_t acol = ((uint32_t)(kk * 32) + a_sel) ^ xr;
            const uint32_t bcol = ((uint32_t)(kk * 32) + b_sel) ^ xr;

            uint32_t a[2][4];
            #pragma unroll
            for (int mt = 0; mt < 2; mt++) {
                ldsm_x4(a[mt], As + a_row[mt] + acol);
                #pragma unroll
                for (int j = 0; j < 4; j++) a[mt][j] = tf32u(a[mt][j]);
            }
            uint32_t bb[2][4];
            #pragma unroll
            for (int ntp = 0; ntp < 2; ntp++)
                ldsm_x4(bb[ntp], Bs + b_row[ntp] + bcol);   // already tf32 bits
            #pragma unroll
            for (int ntp = 0; ntp < 2; ntp++) {
                mma_tf32(acc[0][2 * ntp],     a[0], bb[ntp][0], bb[ntp][1]);
                mma_tf32(acc[1][2 * ntp],     a[1], bb[ntp][0], bb[ntp][1]);
                mma_tf32(acc[0][2 * ntp + 1], a[0], bb[ntp][2], bb[ntp][3]);
                mma_tf32(acc[1][2 * ntp + 1], a[1], bb[ntp][2], bb[ntp][3]);
            }
        }

        stage = (stage == NSTAGE - 1) ? 0 : stage + 1;
        dst   = (dst == NSTAGE - 1) ? 0 : dst + 1;
    }

    // ---- epilogue: bias + relu, float2 stores
    const int m_base = m0 + wm * 32;
    const int n_base = n0 + wn * 32;
    #pragma unroll
    for (int nt = 0; nt < 4; nt++) {
        const int col = n_base + nt * 8 + 2 * t;
        const float2 bv = *reinterpret_cast<const float2*>(bias + col);
        #pragma unroll
        for (int mt = 0; mt < 2; mt++) {
            const int row0 = m_base + mt * 16 + g;
            float2 v0;
            v0.x = fmaxf(acc[mt][nt][0] + bv.x, 0.0f);
            v0.y = fmaxf(acc[mt][nt][1] + bv.y, 0.0f);
            *reinterpret_cast<float2*>(out + (size_t)row0 * DN + col) = v0;
            float2 v1;
            v1.x = fmaxf(acc[mt][nt][2] + bv.x, 0.0f);
            v1.y = fmaxf(acc[mt][nt][3] + bv.y, 0.0f);
            *reinterpret_cast<float2*>(out + (size_t)(row0 + 8) * DN + col) = v1;
        }
    }
}

// ---------------------------------------------------------------------------
extern "C" void kernel_launch(void* const* d_in, const int* in_sizes, int n_in,
                              void* d_out, int out_size) {
    const float* x = (const float*)d_in[0];
    const float* W = (const float*)d_in[1];
    const float* b = (const float*)d_in[2];
    float* out = (float*)d_out;

    int Brows = in_sizes[0] / DK;     // 131072
    dim3 grid(DN / BN, Brows / BM);   // (2, 2048): N-split fastest-varying

    convert_W_kernel<<<DN * DK / 4 / 256, 256>>>(W);   // 64 blocks

    cudaFuncSetAttribute(gemm_relu_tf32_kernel,
                         cudaFuncAttributeMaxDynamicSharedMemorySize, SMEM_DYN);
    gemm_relu_tf32_kernel<<<grid, THREADS, SMEM_DYN>>>(x, b, out);
}

// round 10
// speedup vs baseline: 1.4037x; 1.0037x over previous
#include <cuda_runtime.h>
#include <cstdint>

// ============================================================================
// relu(x @ W^T + b): M=131072, N=256, K=256, fp32.  Base sm_103 target.
// mma.sync.m16n8k8.tf32. CUTLASS-style operating point:
//   CTA 128x128, 4 warps, warp tile 64x64 (acc=128 regs/lane), 2 CTAs/SM.
//   Latency hidden by ILP (32-MMA runs per kk), not TLP.
//   LDS fragment traffic: 128 B/MMA (vs 192 R5, 256 R9).
// KC=32, 3-stage cp.async (prefetch 2), rolled kc loop (I$-friendly).
// W pre-converted to tf32(RNA) once -> zero B cvt in mainloop.
// grid(2, 1024): N-halves of one m-tile co-resident => x DRAM-read ~once.
// ============================================================================

static constexpr int DK = 256;
static constexpr int DN = 256;
static constexpr int BM = 128;
static constexpr int BN = 128;
static constexpr int KC = 32;                 // 32 fp32 = 128B row
static constexpr int THREADS = 128;
static constexpr int NSTAGE = 3;

static constexpr int A_BYTES = BM * KC * 4;   // 16384
static constexpr int B_BYTES = BN * KC * 4;   // 16384
static constexpr int STAGE_BYTES = A_BYTES + B_BYTES;   // 32768
static constexpr int SMEM_DYN = NSTAGE * STAGE_BYTES;   // 98304

__device__ float W_cvt[DN * DK];              // 256KB static scratch (tf32 bits)

// ---------------------------------------------------------------------------
__device__ __forceinline__ uint32_t smem_u32(const void* p) {
    uint32_t a;
    asm("{ .reg .u64 t; cvta.to.shared.u64 t, %1; cvt.u32.u64 %0, t; }" : "=r"(a) : "l"(p));
    return a;
}
__device__ __forceinline__ void cp_async16(uint32_t dst, const void* src) {
    asm volatile("cp.async.cg.shared.global [%0], [%1], 16;" :: "r"(dst), "l"(src));
}
__device__ __forceinline__ void ldsm_x4(uint32_t* d, uint32_t addr) {
    asm volatile("ldmatrix.sync.aligned.m8n8.x4.shared.b16 {%0,%1,%2,%3}, [%4];"
                 : "=r"(d[0]), "=r"(d[1]), "=r"(d[2]), "=r"(d[3]) : "r"(addr));
}
__device__ __forceinline__ uint32_t tf32r(float v) {
    uint32_t r;
    asm("cvt.rna.tf32.f32 %0, %1;" : "=r"(r) : "f"(v));
    return r;
}
__device__ __forceinline__ uint32_t tf32u(uint32_t v) {
    uint32_t r;
    asm("cvt.rna.tf32.f32 %0, %1;" : "=r"(r) : "f"(__uint_as_float(v)));
    return r;
}
__device__ __forceinline__ void mma_tf32(float* d, const uint32_t* a,
                                         uint32_t b0, uint32_t b1) {
    asm volatile(
        "mma.sync.aligned.m16n8k8.row.col.f32.tf32.tf32.f32 "
        "{%0,%1,%2,%3}, {%4,%5,%6,%7}, {%8,%9}, {%0,%1,%2,%3};"
        : "+f"(d[0]), "+f"(d[1]), "+f"(d[2]), "+f"(d[3])
        : "r"(a[0]), "r"(a[1]), "r"(a[2]), "r"(a[3]), "r"(b0), "r"(b1));
}
__device__ __forceinline__ uint32_t swz(int row, int seg) {
    return (uint32_t)row * 128u + (uint32_t)((seg * 16) ^ ((row & 7) * 16));
}

// ---------------------------------------------------------------------------
__global__ void convert_W_kernel(const float* __restrict__ W) {
    int i = blockIdx.x * 256 + threadIdx.x;
    float4 v = reinterpret_cast<const float4*>(W)[i];
    float4 o;
    o.x = __uint_as_float(tf32r(v.x));
    o.y = __uint_as_float(tf32r(v.y));
    o.z = __uint_as_float(tf32r(v.z));
    o.w = __uint_as_float(tf32r(v.w));
    reinterpret_cast<float4*>(W_cvt)[i] = o;
}

// ---------------------------------------------------------------------------
__global__ __launch_bounds__(THREADS, 2)
void gemm_relu_tf32_kernel(const float* __restrict__ x,
                           const float* __restrict__ bias, float* __restrict__ out) {
    extern __shared__ __align__(1024) char smem_raw[];
    const uint32_t base = smem_u32(smem_raw);

    const int tid = threadIdx.x;
    const int wid = tid >> 5;      // 0..3
    const int lid = tid & 31;
    const int g   = lid >> 2;
    const int t   = lid & 3;
    const int wm  = wid & 1;       // warp m-tile (2 x 64 rows)
    const int wn  = wid >> 1;      // warp n-tile (2 x 64 cols)
    const int n0  = blockIdx.x * BN;      // N fastest-varying -> L2 x reuse
    const int m0  = blockIdx.y * BM;
    const float* Wp = W_cvt + (size_t)n0 * DK;

    // ldmatrix lane role
    const int mx = lid >> 3;
    const int r  = lid & 7;
    const uint32_t xr = (uint32_t)(r * 16);

    uint32_t a_row[4], b_row[4];
    #pragma unroll
    for (int mt = 0; mt < 4; mt++)
        a_row[mt] = (uint32_t)(wm * 64 + mt * 16 + (mx & 1) * 8 + r) * 128u;
    #pragma unroll
    for (int ntp = 0; ntp < 4; ntp++)
        b_row[ntp] = (uint32_t)(wn * 64 + ntp * 16 + (mx >> 1) * 8 + r) * 128u;
    const uint32_t a_sel = (uint32_t)((mx >> 1) * 16);
    const uint32_t b_sel = (uint32_t)((mx & 1) * 16);

    // load roles: A 8 float4/thread, B 8 float4/thread per chunk
    const int lrow = tid >> 3;       // 0..15
    const int lseg = tid & 7;        // 0..7

    // ---- prologue: stage chunks 0,1 into stages 0,1
    #pragma unroll
    for (int pc = 0; pc < 2; pc++) {
        const uint32_t S = base + (uint32_t)pc * STAGE_BYTES;
        const int k0 = pc * KC;
        #pragma unroll
        for (int i = 0; i < 8; i++) {
            int row = i * 16 + lrow;
            cp_async16(S + swz(row, lseg), x + (size_t)(m0 + row) * DK + k0 + lseg * 4);
        }
        #pragma unroll
        for (int i = 0; i < 8; i++) {
            int row = i * 16 + lrow;
            cp_async16(S + A_BYTES + swz(row, lseg), Wp + (size_t)row * DK + k0 + lseg * 4);
        }
        asm volatile("cp.async.commit_group;" ::: "memory");
    }

    float acc[4][8][4];              // 128 accumulators: warp tile 64x64
    #pragma unroll
    for (int mt = 0; mt < 4; mt++)
        #pragma unroll
        for (int nt = 0; nt < 8; nt++)
            #pragma unroll
            for (int j = 0; j < 4; j++) acc[mt][nt][j] = 0.0f;

    int stage = 0, dst = 2;
    #pragma unroll 1
    for (int kc = 0; kc < 8; kc++) {
        if (kc < 7)
            asm volatile("cp.async.wait_group 1;" ::: "memory");
        else
            asm volatile("cp.async.wait_group 0;" ::: "memory");  // drain last chunk
        __syncthreads();

        const uint32_t As = base + (uint32_t)stage * STAGE_BYTES;
        const uint32_t Bs = As + A_BYTES;

        if (kc < 6) {
            const uint32_t Ad = base + (uint32_t)dst * STAGE_BYTES;
            const int k2 = (kc + 2) * KC;
            #pragma unroll
            for (int i = 0; i < 8; i++) {
                int row = i * 16 + lrow;
                cp_async16(Ad + swz(row, lseg),
                           x + (size_t)(m0 + row) * DK + k2 + lseg * 4);
            }
            #pragma unroll
            for (int i = 0; i < 8; i++) {
                int row = i * 16 + lrow;
                cp_async16(Ad + A_BYTES + swz(row, lseg),
                           Wp + (size_t)row * DK + k2 + lseg * 4);
            }
            asm volatile("cp.async.commit_group;" ::: "memory");
        }

        #pragma unroll
        for (int kk = 0; kk < 4; kk++) {
            const uint32_t acol = ((uint32_t)(kk * 32) + a_sel) ^ xr;
            const uint32_t bcol = ((uint32_t)(kk * 32) + b_sel) ^ xr;

            uint32_t a[4][4];
            #pragma unroll
            for (int mt = 0; mt < 4; mt++) {
                ldsm_x4(a[mt], As + a_row[mt] + acol);
                #pragma unroll
                for (int j = 0; j < 4; j++) a[mt][j] = tf32u(a[mt][j]);
            }
            uint32_t bb[4][4];
            #pragma unroll
            for (int ntp = 0; ntp < 4; ntp++)
                ldsm_x4(bb[ntp], Bs + b_row[ntp] + bcol);   // already tf32 bits

            #pragma unroll
            for (int mt = 0; mt < 4; mt++) {
                #pragma unroll
                for (int ntp = 0; ntp < 4; ntp++) {
                    mma_tf32(acc[mt][2 * ntp],     a[mt], bb[ntp][0], bb[ntp][1]);
                    mma_tf32(acc[mt][2 * ntp + 1], a[mt], bb[ntp][2], bb[ntp][3]);
                }
            }
        }

        stage = (stage == NSTAGE - 1) ? 0 : stage + 1;
        dst   = (dst == NSTAGE - 1) ? 0 : dst + 1;
    }

    // ---- epilogue: bias + relu, float2 stores
    const int m_base = m0 + wm * 64;
    const int n_base = n0 + wn * 64;
    #pragma unroll
    for (int nt = 0; nt < 8; nt++) {
        const int col = n_base + nt * 8 + 2 * t;
        const float2 bv = *reinterpret_cast<const float2*>(bias + col);
        #pragma unroll
        for (int mt = 0; mt < 4; mt++) {
            const int row0 = m_base + mt * 16 + g;
            float2 v0;
            v0.x = fmaxf(acc[mt][nt][0] + bv.x, 0.0f);
            v0.y = fmaxf(acc[mt][nt][1] + bv.y, 0.0f);
            *reinterpret_cast<float2*>(out + (size_t)row0 * DN + col) = v0;
            float2 v1;
            v1.x = fmaxf(acc[mt][nt][2] + bv.x, 0.0f);
            v1.y = fmaxf(acc[mt][nt][3] + bv.y, 0.0f);
            *reinterpret_cast<float2*>(out + (size_t)(row0 + 8) * DN + col) = v1;
        }
    }
}

// ---------------------------------------------------------------------------
extern "C" void kernel_launch(void* const* d_in, const int* in_sizes, int n_in,
                              void* d_out, int out_size) {
    const float* x = (const float*)d_in[0];
    const float* W = (const float*)d_in[1];
    const float* b = (const float*)d_in[2];
    float* out = (float*)d_out;

    int Brows = in_sizes[0] / DK;     // 131072
    dim3 grid(DN / BN, Brows / BM);   // (2, 1024)

    convert_W_kernel<<<DN * DK / 4 / 256, 256>>>(W);   // 64 blocks

    cudaFuncSetAttribute(gemm_relu_tf32_kernel,
                         cudaFuncAttributeMaxDynamicSharedMemorySize, SMEM_DYN);
    gemm_relu_tf32_kernel<<<grid, THREADS, SMEM_DYN>>>(x, b, out);
}

// round 13
// speedup vs baseline: 1.7453x; 1.2434x over previous
#include <cuda_runtime.h>
#include <cuda_fp16.h>
#include <cstdint>

// ============================================================================
// relu(x @ W^T + b): M=131072, N=256, K=256, fp32.  Base sm_103 target.
// R11: mma.sync.m16n8k16.f16 (fp16 mantissa == tf32 mantissa => same accuracy,
// HALF the HMMA instructions). CTA 128x128, 4 warps, warp tile 64x64,
// KC=32, 3-stage cp.async, 2 CTAs/SM, grid(2,1024) for L2 x reuse.
// B: W pre-converted to fp16 -> cp.async -> ldmatrix -> MMA (zero cvt).
// A: fp32 smem -> ld.shared.v2 -> cvt.rn.f16x2 pack in-loop.
// ============================================================================

static constexpr int DK = 256;
static constexpr int DN = 256;
static constexpr int BM = 128;
static constexpr int BN = 128;
static constexpr int KC = 32;                 // K per chunk
static constexpr int THREADS = 128;
static constexpr int NSTAGE = 3;

static constexpr int A_BYTES = BM * KC * 4;   // 16384 (fp32)
static constexpr int B_BYTES = BN * 128;      // 16384 (fp16, rows padded to 128B)
static constexpr int STAGE_BYTES = A_BYTES + B_BYTES;   // 32768
static constexpr int SMEM_DYN = NSTAGE * STAGE_BYTES;   // 98304

__device__ __half W_h[DN * DK];               // 128KB fp16 weight scratch

// ---------------------------------------------------------------------------
__device__ __forceinline__ uint32_t smem_u32(const void* p) {
    uint32_t a;
    asm("{ .reg .u64 t; cvta.to.shared.u64 t, %1; cvt.u32.u64 %0, t; }" : "=r"(a) : "l"(p));
    return a;
}
__device__ __forceinline__ void cp_async16(uint32_t dst, const void* src) {
    asm volatile("cp.async.cg.shared.global [%0], [%1], 16;" :: "r"(dst), "l"(src));
}
__device__ __forceinline__ void ldsm_x4(uint32_t* d, uint32_t addr) {
    asm volatile("ldmatrix.sync.aligned.m8n8.x4.shared.b16 {%0,%1,%2,%3}, [%4];"
                 : "=r"(d[0]), "=r"(d[1]), "=r"(d[2]), "=r"(d[3]) : "r"(addr));
}
__device__ __forceinline__ uint32_t pack_f16(float hi, float lo) {
    uint32_t d;
    asm("cvt.rn.f16x2.f32 %0, %1, %2;" : "=r"(d) : "f"(hi), "f"(lo));
    return d;
}
__device__ __forceinline__ float2 lds64(uint32_t addr) {
    float2 v;
    asm volatile("ld.shared.v2.f32 {%0, %1}, [%2];" : "=f"(v.x), "=f"(v.y) : "r"(addr));
    return v;
}
__device__ __forceinline__ void mma_f16(float* d, const uint32_t* a,
                                        uint32_t b0, uint32_t b1) {
    asm volatile(
        "mma.sync.aligned.m16n8k16.row.col.f32.f16.f16.f32 "
        "{%0,%1,%2,%3}, {%4,%5,%6,%7}, {%8,%9}, {%0,%1,%2,%3};"
        : "+f"(d[0]), "+f"(d[1]), "+f"(d[2]), "+f"(d[3])
        : "r"(a[0]), "r"(a[1]), "r"(a[2]), "r"(a[3]), "r"(b0), "r"(b1));
}
// swizzled byte offset for fp32 A rows (128B rows)
__device__ __forceinline__ uint32_t swzA(int row, int seg) {
    return (uint32_t)row * 128u + (uint32_t)((seg * 16) ^ ((row & 7) * 16));
}
// swizzled byte offset for fp16 B rows (64B data in 128B padded rows)
__device__ __forceinline__ uint32_t swzB(int row, int seg) {
    return (uint32_t)row * 128u + (uint32_t)((seg * 16) ^ ((row & 7) * 16));
}

// ---------------------------------------------------------------------------
// pre-pass: W (fp32) -> fp16
__global__ void convert_W_kernel(const float* __restrict__ W) {
    int i = blockIdx.x * 256 + threadIdx.x;     // 16384 float4
    float4 v = reinterpret_cast<const float4*>(W)[i];
    uint2 o;
    o.x = pack_f16(v.y, v.x);
    o.y = pack_f16(v.w, v.z);
    reinterpret_cast<uint2*>(W_h)[i] = o;
}

// ---------------------------------------------------------------------------
__global__ __launch_bounds__(THREADS, 2)
void gemm_relu_f16_kernel(const float* __restrict__ x,
                          const float* __restrict__ bias, float* __restrict__ out) {
    extern __shared__ __align__(1024) char smem_raw[];
    const uint32_t base = smem_u32(smem_raw);

    const int tid = threadIdx.x;
    const int wid = tid >> 5;      // 0..3
    const int lid = tid & 31;
    const int g   = lid >> 2;      // 0..7
    const int t   = lid & 3;       // 0..3
    const int wm  = wid & 1;       // warp m-tile (2 x 64 rows)
    const int wn  = wid >> 1;      // warp n-tile (2 x 64 cols)
    const int n0  = blockIdx.x * BN;      // N fastest-varying -> L2 x reuse
    const int m0  = blockIdx.y * BM;
    const __half* Wp = W_h + (size_t)n0 * DK;

    // ldmatrix lane role for B
    const int mx = lid >> 3;       // matrix index 0..3
    const int r  = lid & 7;
    const uint32_t xr = (uint32_t)(r * 16);
    // matrices: m0 = n(+0..7) kLo, m1 = n(+8..15) kLo, m2 = n(+0..7) kHi, m3 = n(+8..15) kHi
    uint32_t b_row[4];
    #pragma unroll
    for (int ntp = 0; ntp < 4; ntp++)
        b_row[ntp] = (uint32_t)(wn * 64 + ntp * 16 + (mx & 1) * 8 + r) * 128u;
    const uint32_t b_sel = (uint32_t)((mx >> 1) * 16);

    // A fragment LDS base rows
    uint32_t aL_row[4], aH_row[4];
    #pragma unroll
    for (int mt = 0; mt < 4; mt++) {
        aL_row[mt] = (uint32_t)(wm * 64 + mt * 16 + g) * 128u;
        aH_row[mt] = (uint32_t)(wm * 64 + mt * 16 + g + 8) * 128u;
    }
    const uint32_t xg = (uint32_t)(g * 16);

    // load roles
    const int lrowA = tid >> 3;      // 0..15
    const int lsegA = tid & 7;       // 0..7
    const int lrowB = tid >> 2;      // 0..31
    const int lsegB = tid & 3;       // 0..3

    // ---- prologue: stage chunks 0,1 into stages 0,1
    #pragma unroll
    for (int pc = 0; pc < 2; pc++) {
        const uint32_t S = base + (uint32_t)pc * STAGE_BYTES;
        const int k0 = pc * KC;
        #pragma unroll
        for (int i = 0; i < 8; i++) {
            int row = i * 16 + lrowA;
            cp_async16(S + swzA(row, lsegA), x + (size_t)(m0 + row) * DK + k0 + lsegA * 4);
        }
        #pragma unroll
        for (int i = 0; i < 4; i++) {
            int row = i * 32 + lrowB;
            cp_async16(S + A_BYTES + swzB(row, lsegB),
                       Wp + (size_t)row * DK + k0 + lsegB * 8);
        }
        asm volatile("cp.async.commit_group;" ::: "memory");
    }

    float acc[4][8][4];              // warp tile 64x64
    #pragma unroll
    for (int mt = 0; mt < 4; mt++)
        #pragma unroll
        for (int nt = 0; nt < 8; nt++)
            #pragma unroll
            for (int j = 0; j < 4; j++) acc[mt][nt][j] = 0.0f;

    int stage = 0, dst = 2;
    #pragma unroll 1
    for (int kc = 0; kc < 8; kc++) {
        if (kc < 7)
            asm volatile("cp.async.wait_group 1;" ::: "memory");
        else
            asm volatile("cp.async.wait_group 0;" ::: "memory");  // drain last chunk
        __syncthreads();

        const uint32_t As = base + (uint32_t)stage * STAGE_BYTES;
        const uint32_t Bs = As + A_BYTES;

        if (kc < 6) {
            const uint32_t Ad = base + (uint32_t)dst * STAGE_BYTES;
            const int k2 = (kc + 2) * KC;
            #pragma unroll
            for (int i = 0; i < 8; i++) {
                int row = i * 16 + lrowA;
                cp_async16(Ad + swzA(row, lsegA),
                           x + (size_t)(m0 + row) * DK + k2 + lsegA * 4);
            }
            #pragma unroll
            for (int i = 0; i < 4; i++) {
                int row = i * 32 + lrowB;
                cp_async16(Ad + A_BYTES + swzB(row, lsegB),
                           Wp + (size_t)row * DK + k2 + lsegB * 8);
            }
            asm volatile("cp.async.commit_group;" ::: "memory");
        }

        #pragma unroll
        for (int kk = 0; kk < 2; kk++) {      // 2 x k16 per chunk
            // ---- B fragments: 4 n16 tiles, direct fp16 ldmatrix
            uint32_t bb[4][4];
            const uint32_t bcol = ((uint32_t)(kk * 32) + b_sel) ^ xr;
            #pragma unroll
            for (int ntp = 0; ntp < 4; ntp++)
                ldsm_x4(bb[ntp], Bs + b_row[ntp] + bcol);

            // ---- A fragments: fp32 LDS.64 pairs -> fp16x2 pack
            uint32_t a[4][4];
            const uint32_t cLo = ((uint32_t)(kk * 64 + t * 8));
            #pragma unroll
            for (int mt = 0; mt < 4; mt++) {
                float2 v00 = lds64(As + aL_row[mt] + (cLo ^ xg));
                float2 v01 = lds64(As + aH_row[mt] + (cLo ^ xg));
                float2 v10 = lds64(As + aL_row[mt] + ((cLo + 32) ^ xg));
                float2 v11 = lds64(As + aH_row[mt] + ((cLo + 32) ^ xg));
                a[mt][0] = pack_f16(v00.y, v00.x);
                a[mt][1] = pack_f16(v01.y, v01.x);
                a[mt][2] = pack_f16(v10.y, v10.x);
                a[mt][3] = pack_f16(v11.y, v11.x);
            }

            // ---- 32 MMAs (m16n8k16)
            #pragma unroll
            for (int mt = 0; mt < 4; mt++) {
                #pragma unroll
                for (int ntp = 0; ntp < 4; ntp++) {
                    mma_f16(acc[mt][2 * ntp],     a[mt], bb[ntp][0], bb[ntp][2]);
                    mma_f16(acc[mt][2 * ntp + 1], a[mt], bb[ntp][1], bb[ntp][3]);
                }
            }
        }

        stage = (stage == NSTAGE - 1) ? 0 : stage + 1;
        dst   = (dst == NSTAGE - 1) ? 0 : dst + 1;
    }

    // ---- epilogue: bias + relu, float2 stores
    const int m_base = m0 + wm * 64;
    const int n_base = n0 + wn * 64;
    #pragma unroll
    for (int nt = 0; nt < 8; nt++) {
        const int col = n_base + nt * 8 + 2 * t;
        const float2 bv = *reinterpret_cast<const float2*>(bias + col);
        #pragma unroll
        for (int mt = 0; mt < 4; mt++) {
            const int row0 = m_base + mt * 16 + g;
            float2 v0;
            v0.x = fmaxf(acc[mt][nt][0] + bv.x, 0.0f);
            v0.y = fmaxf(acc[mt][nt][1] + bv.y, 0.0f);
            *reinterpret_cast<float2*>(out + (size_t)row0 * DN + col) = v0;
            float2 v1;
            v1.x = fmaxf(acc[mt][nt][2] + bv.x, 0.0f);
            v1.y = fmaxf(acc[mt][nt][3] + bv.y, 0.0f);
            *reinterpret_cast<float2*>(out + (size_t)(row0 + 8) * DN + col) = v1;
        }
    }
}

// ---------------------------------------------------------------------------
extern "C" void kernel_launch(void* const* d_in, const int* in_sizes, int n_in,
                              void* d_out, int out_size) {
    const float* x = (const float*)d_in[0];
    const float* W = (const float*)d_in[1];
    const float* b = (const float*)d_in[2];
    float* out = (float*)d_out;

    int Brows = in_sizes[0] / DK;     // 131072
    dim3 grid(DN / BN, Brows / BM);   // (2, 1024)

    convert_W_kernel<<<DN * DK / 4 / 256, 256>>>(W);   // 64 blocks

    cudaFuncSetAttribute(gemm_relu_f16_kernel,
                         cudaFuncAttributeMaxDynamicSharedMemorySize, SMEM_DYN);
    gemm_relu_f16_kernel<<<grid, THREADS, SMEM_DYN>>>(x, b, out);
}